// round 2
// baseline (speedup 1.0000x reference)
#include <cuda_runtime.h>

// MMDLayer: out[t,s] = (1 - ||x_t - C[511+t-s]||^2 / 128)^3
// C[k] = init[511-k] (k<512) else x[k-512].
// Banded GEMM via ||a-b||^2 = ||a||^2+||b||^2-2ab, packed f32x2 FFMA2 inner loop.

#define T_LEN 2048
#define S_LEN 512
#define D_LEN 128
#define BT 32
#define BK 64
#define PADW 132          // smem row stride in floats (528B, 16B-aligned, conflict-free)
#define NKT 9             // k-tiles per t-block: covers band width 32+511 <= 576

__device__ __forceinline__ unsigned long long ffma2(unsigned long long a,
                                                    unsigned long long b,
                                                    unsigned long long c)
{
    unsigned long long d;
    asm("fma.rn.f32x2 %0, %1, %2, %3;" : "=l"(d) : "l"(a), "l"(b), "l"(c));
    return d;
}

__global__ __launch_bounds__(128, 4)
void mmd_band_kernel(const float* __restrict__ x,
                     const float* __restrict__ init,
                     float* __restrict__ out)
{
    extern __shared__ float sm[];
    float* As  = sm;                          // [BT][PADW]
    float* Bs  = sm + BT * PADW;              // [BK][PADW]
    float* nrm = sm + (BT + BK) * PADW;       // [96]: 0..31 A norms, 32..95 B norms

    const int t0 = blockIdx.y * BT;
    const int k0 = t0 + blockIdx.x * BK;
    const int tid = threadIdx.x;

    // ---- Load A tile (32 rows x 128 f32), coalesced float4 ----
    #pragma unroll
    for (int idx = tid; idx < BT * 32; idx += 128) {
        int r = idx >> 5;
        int c = idx & 31;
        float4 v = reinterpret_cast<const float4*>(x + (size_t)(t0 + r) * D_LEN)[c];
        reinterpret_cast<float4*>(As + r * PADW)[c] = v;
    }
    // ---- Load B tile (64 virtual C rows), clamp k (clamped rows are masked out) ----
    #pragma unroll
    for (int idx = tid; idx < BK * 32; idx += 128) {
        int r = idx >> 5;
        int c = idx & 31;
        int k = k0 + r;
        if (k > T_LEN + S_LEN - 1) k = T_LEN + S_LEN - 1;   // 2559
        const float* src = (k < S_LEN) ? (init + (size_t)(S_LEN - 1 - k) * D_LEN)
                                       : (x    + (size_t)(k - S_LEN) * D_LEN);
        float4 v = reinterpret_cast<const float4*>(src)[c];
        reinterpret_cast<float4*>(Bs + r * PADW)[c] = v;
    }
    __syncthreads();

    // ---- Per-row squared norms from smem ----
    if (tid < BT + BK) {
        const float* row = (tid < BT) ? (As + tid * PADW) : (Bs + (tid - BT) * PADW);
        float acc = 0.f;
        #pragma unroll
        for (int c = 0; c < 32; c++) {
            float4 v = reinterpret_cast<const float4*>(row)[c];
            acc += v.x * v.x;
            acc += v.y * v.y;
            acc += v.z * v.z;
            acc += v.w * v.w;
        }
        nrm[tid] = acc;
    }
    __syncthreads();

    const int tx = tid & 15;   // k-lane: 4 micro, stride 16 -> 64 k
    const int ty = tid >> 4;   // t-lane: 4 micro, stride 8  -> 32 t

    // acc2[i][j]: packed pair of partial dots (lanes 0/1 of f32x2)
    unsigned long long acc2[4][4];
    #pragma unroll
    for (int i = 0; i < 4; i++)
        #pragma unroll
        for (int j = 0; j < 4; j++)
            acc2[i][j] = 0ULL;   // two packed +0.0f

    // ---- Main loop: 32 chunks of 4 d-values (2 f32x2 pairs) ----
    #pragma unroll 4
    for (int c = 0; c < 32; c++) {
        ulonglong2 a[4], b[4];
        #pragma unroll
        for (int i = 0; i < 4; i++)
            a[i] = *reinterpret_cast<const ulonglong2*>(As + (ty + 8 * i) * PADW + 4 * c);
        #pragma unroll
        for (int j = 0; j < 4; j++)
            b[j] = *reinterpret_cast<const ulonglong2*>(Bs + (tx + 16 * j) * PADW + 4 * c);
        #pragma unroll
        for (int i = 0; i < 4; i++) {
            #pragma unroll
            for (int j = 0; j < 4; j++) {
                acc2[i][j] = ffma2(a[i].x, b[j].x, acc2[i][j]);
                acc2[i][j] = ffma2(a[i].y, b[j].y, acc2[i][j]);
            }
        }
    }

    // ---- Epilogue ----
    #pragma unroll
    for (int i = 0; i < 4; i++) {
        const int rt = ty + 8 * i;
        const int t  = t0 + rt;
        const float nA = nrm[rt];
        #pragma unroll
        for (int j = 0; j < 4; j++) {
            const int rk = tx + 16 * j;
            const int k  = k0 + rk;
            const int s  = 511 + t - k;
            if (s >= 0 && s < S_LEN) {
                float2 p = *reinterpret_cast<float2*>(&acc2[i][j]);
                float dot = p.x + p.y;
                float d2 = nA + nrm[BT + rk] - 2.0f * dot;
                float u  = 1.0f - d2 * (1.0f / 128.0f);
                out[(size_t)t * S_LEN + s] = u * u * u;
            }
        }
    }
}

extern "C" void kernel_launch(void* const* d_in, const int* in_sizes, int n_in,
                              void* d_out, int out_size)
{
    const float* x    = (const float*)d_in[0];   // (1, 2048, 1, 128) fp32
    const float* init = (const float*)d_in[1];   // (512, 128) fp32
    float* out = (float*)d_out;                  // (1, 2048, 512) fp32

    const int smem_bytes = ((BT + BK) * PADW + BT + BK) * (int)sizeof(float); // 51072 B
    cudaFuncSetAttribute(mmd_band_kernel,
                         cudaFuncAttributeMaxDynamicSharedMemorySize, smem_bytes);

    dim3 grid(NKT, T_LEN / BT);   // (9, 64) = 576 blocks -> ~4 CTAs/SM, single wave
    mmd_band_kernel<<<grid, 128, smem_bytes>>>(x, init, out);
}

// round 3
// speedup vs baseline: 1.1555x; 1.1555x over previous
#include <cuda_runtime.h>

// MMDLayer: out[t,s] = (1 - ||x_t - C[511+t-s]||^2 / 128)^3
// C[k] = init[511-k] (k<512) else x[k-512].
// Banded GEMM via ||a-b||^2 = ||a||^2+||b||^2-2ab; packed f32x2 FFMA2 inner loop.

#define T_LEN 2048
#define S_LEN 512
#define D_LEN 128
#define BT 64
#define BK 64
#define PADW 132          // smem row stride in floats (528B, 16B-aligned)
#define NKT 9             // k-tiles per t-block: band 64+511 <= 576

typedef unsigned long long u64;

__device__ __forceinline__ u64 ffma2(u64 a, u64 b, u64 c)
{
    u64 d;
    asm("fma.rn.f32x2 %0, %1, %2, %3;" : "=l"(d) : "l"(a), "l"(b), "l"(c));
    return d;
}

__global__ __launch_bounds__(128, 3)
void mmd_band_kernel(const float* __restrict__ x,
                     const float* __restrict__ init,
                     float* __restrict__ out)
{
    extern __shared__ float sm[];
    float* As  = sm;                          // [BT][PADW]
    float* Bs  = sm + BT * PADW;              // [BK][PADW]
    float* nrm = sm + (BT + BK) * PADW;       // [128]

    const int t0 = blockIdx.y * BT;
    const int k0 = t0 + blockIdx.x * BK;
    const int tid = threadIdx.x;

    // ---- Load A tile (64 x 128 f32), coalesced float4 ----
    #pragma unroll
    for (int idx = tid; idx < BT * 32; idx += 128) {
        int r = idx >> 5;
        int c = idx & 31;
        float4 v = reinterpret_cast<const float4*>(x + (size_t)(t0 + r) * D_LEN)[c];
        reinterpret_cast<float4*>(As + r * PADW)[c] = v;
    }
    // ---- Load B tile (64 virtual C rows) ----
    #pragma unroll
    for (int idx = tid; idx < BK * 32; idx += 128) {
        int r = idx >> 5;
        int c = idx & 31;
        int k = k0 + r;
        const float* src = (k < S_LEN) ? (init + (size_t)(S_LEN - 1 - k) * D_LEN)
                                       : (x    + (size_t)(k - S_LEN) * D_LEN);
        float4 v = reinterpret_cast<const float4*>(src)[c];
        reinterpret_cast<float4*>(Bs + r * PADW)[c] = v;
    }
    __syncthreads();

    // ---- Per-row squared norms from smem ----
    {
        const float* row = (tid < BT) ? (As + tid * PADW) : (Bs + (tid - BT) * PADW);
        float acc = 0.f;
        #pragma unroll
        for (int c = 0; c < 32; c++) {
            float4 v = reinterpret_cast<const float4*>(row)[c];
            acc += v.x * v.x;
            acc += v.y * v.y;
            acc += v.z * v.z;
            acc += v.w * v.w;
        }
        nrm[tid] = acc;
    }
    __syncthreads();

    const int tx = tid & 15;   // k-lane: 4 micro, stride 16 -> 64 k
    const int ty = tid >> 4;   // t-lane: 8 micro, stride 8  -> 64 t

    // Packed pair accumulators (each holds 2 partial dot lanes over d)
    u64 acc2[8][4];
    #pragma unroll
    for (int i = 0; i < 8; i++)
        #pragma unroll
        for (int j = 0; j < 4; j++)
            acc2[i][j] = 0ULL;

    // ---- Main loop over d in chunks of 4 floats (2 f32x2 pairs) ----
    #pragma unroll 2
    for (int c = 0; c < 32; c++) {
        ulonglong2 a[8], b[4];
        #pragma unroll
        for (int i = 0; i < 8; i++)
            a[i] = *reinterpret_cast<const ulonglong2*>(As + (ty + 8 * i) * PADW + 4 * c);
        #pragma unroll
        for (int j = 0; j < 4; j++)
            b[j] = *reinterpret_cast<const ulonglong2*>(Bs + (tx + 16 * j) * PADW + 4 * c);

        // x-pass: 32 independent FFMA2 (no acc rewritten back-to-back)
        #pragma unroll
        for (int i = 0; i < 8; i++)
            #pragma unroll
            for (int j = 0; j < 4; j++)
                acc2[i][j] = ffma2(a[i].x, b[j].x, acc2[i][j]);
        // y-pass
        #pragma unroll
        for (int i = 0; i < 8; i++)
            #pragma unroll
            for (int j = 0; j < 4; j++)
                acc2[i][j] = ffma2(a[i].y, b[j].y, acc2[i][j]);
    }

    // ---- Epilogue: d2 = nA + nB - 2*(p.x+p.y); out = (1 - d2/128)^3 ----
    #pragma unroll
    for (int i = 0; i < 8; i++) {
        const int rt = ty + 8 * i;
        const int t  = t0 + rt;
        const float nA = nrm[rt];
        #pragma unroll
        for (int j = 0; j < 4; j++) {
            const int rk = tx + 16 * j;
            const int k  = k0 + rk;
            const int s  = 511 + t - k;
            if (s >= 0 && s < S_LEN) {
                float2 p = *reinterpret_cast<float2*>(&acc2[i][j]);
                float dot = p.x + p.y;
                float d2 = nA + nrm[BT + rk] - 2.0f * dot;
                float u  = 1.0f - d2 * (1.0f / 128.0f);
                out[(size_t)t * S_LEN + s] = u * u * u;
            }
        }
    }
}

extern "C" void kernel_launch(void* const* d_in, const int* in_sizes, int n_in,
                              void* d_out, int out_size)
{
    const float* x    = (const float*)d_in[0];   // (1, 2048, 1, 128) fp32
    const float* init = (const float*)d_in[1];   // (512, 128) fp32
    float* out = (float*)d_out;                  // (1, 2048, 512) fp32

    const int smem_bytes = ((BT + BK) * PADW + BT + BK) * (int)sizeof(float); // ~68KB
    cudaFuncSetAttribute(mmd_band_kernel,
                         cudaFuncAttributeMaxDynamicSharedMemorySize, smem_bytes);

    dim3 grid(NKT, T_LEN / BT);   // (9, 32) = 288 blocks
    mmd_band_kernel<<<grid, 128, smem_bytes>>>(x, init, out);
}

// round 4
// speedup vs baseline: 1.1580x; 1.0022x over previous
#include <cuda_runtime.h>

// MMDLayer: out[t,s] = (1 - ||x_t - C[511+t-s]||^2 / 128)^3
// C[k] = init[511-k] (k<512) else x[k-512].
// Banded GEMM via ||a-b||^2 = ||a||^2+||b||^2-2ab; packed f32x2 FFMA2 inner loop.
// 256 threads / 4x4 micro-tile for 4 warps/SMSP latency hiding.

#define T_LEN 2048
#define S_LEN 512
#define D_LEN 128
#define BT 64
#define BK 64
#define PADW 132          // smem row stride in floats (528B, 16B-aligned)
#define NKT 9             // k-tiles per t-block: band 64+511 <= 576
#define NTHR 256

typedef unsigned long long u64;

__device__ __forceinline__ u64 ffma2(u64 a, u64 b, u64 c)
{
    u64 d;
    asm("fma.rn.f32x2 %0, %1, %2, %3;" : "=l"(d) : "l"(a), "l"(b), "l"(c));
    return d;
}

__global__ __launch_bounds__(NTHR, 2)
void mmd_band_kernel(const float* __restrict__ x,
                     const float* __restrict__ init,
                     float* __restrict__ out)
{
    extern __shared__ float sm[];
    float* As  = sm;                          // [BT][PADW]
    float* Bs  = sm + BT * PADW;              // [BK][PADW]
    float* nrm = sm + (BT + BK) * PADW;       // [128]

    const int t0 = blockIdx.y * BT;
    const int k0 = t0 + blockIdx.x * BK;
    const int tid = threadIdx.x;

    // ---- Load A tile (64 x 128 f32), coalesced float4 ----
    #pragma unroll
    for (int idx = tid; idx < BT * 32; idx += NTHR) {
        int r = idx >> 5;
        int c = idx & 31;
        float4 v = reinterpret_cast<const float4*>(x + (size_t)(t0 + r) * D_LEN)[c];
        reinterpret_cast<float4*>(As + r * PADW)[c] = v;
    }
    // ---- Load B tile (64 virtual C rows) ----
    #pragma unroll
    for (int idx = tid; idx < BK * 32; idx += NTHR) {
        int r = idx >> 5;
        int c = idx & 31;
        int k = k0 + r;
        const float* src = (k < S_LEN) ? (init + (size_t)(S_LEN - 1 - k) * D_LEN)
                                       : (x    + (size_t)(k - S_LEN) * D_LEN);
        float4 v = reinterpret_cast<const float4*>(src)[c];
        reinterpret_cast<float4*>(Bs + r * PADW)[c] = v;
    }
    __syncthreads();

    // ---- Per-row squared norms from smem (threads 0..127) ----
    if (tid < BT + BK) {
        const float* row = (tid < BT) ? (As + tid * PADW) : (Bs + (tid - BT) * PADW);
        float acc = 0.f;
        #pragma unroll
        for (int c = 0; c < 32; c++) {
            float4 v = reinterpret_cast<const float4*>(row)[c];
            acc += v.x * v.x;
            acc += v.y * v.y;
            acc += v.z * v.z;
            acc += v.w * v.w;
        }
        nrm[tid] = acc;
    }
    __syncthreads();

    const int tx = tid & 15;   // k-lane: 4 micro, stride 16 -> 64 k
    const int ty = tid >> 4;   // t-lane: 4 micro, stride 16 -> 64 t

    // Packed pair accumulators (2 partial dot lanes over d each)
    u64 acc2[4][4];
    #pragma unroll
    for (int i = 0; i < 4; i++)
        #pragma unroll
        for (int j = 0; j < 4; j++)
            acc2[i][j] = 0ULL;

    // ---- Main loop over d in chunks of 4 floats (2 f32x2 pairs) ----
    #pragma unroll 4
    for (int c = 0; c < 32; c++) {
        ulonglong2 a[4], b[4];
        #pragma unroll
        for (int i = 0; i < 4; i++)
            a[i] = *reinterpret_cast<const ulonglong2*>(As + (ty + 16 * i) * PADW + 4 * c);
        #pragma unroll
        for (int j = 0; j < 4; j++)
            b[j] = *reinterpret_cast<const ulonglong2*>(Bs + (tx + 16 * j) * PADW + 4 * c);

        // x-pass then y-pass: each acc rewritten at distance 16 instrs (lat 4 safe)
        #pragma unroll
        for (int i = 0; i < 4; i++)
            #pragma unroll
            for (int j = 0; j < 4; j++)
                acc2[i][j] = ffma2(a[i].x, b[j].x, acc2[i][j]);
        #pragma unroll
        for (int i = 0; i < 4; i++)
            #pragma unroll
            for (int j = 0; j < 4; j++)
                acc2[i][j] = ffma2(a[i].y, b[j].y, acc2[i][j]);
    }

    // ---- Epilogue: d2 = nA + nB - 2*(p.x+p.y); out = (1 - d2/128)^3 ----
    #pragma unroll
    for (int i = 0; i < 4; i++) {
        const int rt = ty + 16 * i;
        const int t  = t0 + rt;
        const float nA = nrm[rt];
        #pragma unroll
        for (int j = 0; j < 4; j++) {
            const int rk = tx + 16 * j;
            const int k  = k0 + rk;
            const int s  = 511 + t - k;
            if (s >= 0 && s < S_LEN) {
                float2 p = *reinterpret_cast<float2*>(&acc2[i][j]);
                float dot = p.x + p.y;
                float d2 = nA + nrm[BT + rk] - 2.0f * dot;
                float u  = 1.0f - d2 * (1.0f / 128.0f);
                out[(size_t)t * S_LEN + s] = u * u * u;
            }
        }
    }
}

extern "C" void kernel_launch(void* const* d_in, const int* in_sizes, int n_in,
                              void* d_out, int out_size)
{
    const float* x    = (const float*)d_in[0];   // (1, 2048, 1, 128) fp32
    const float* init = (const float*)d_in[1];   // (512, 128) fp32
    float* out = (float*)d_out;                  // (1, 2048, 512) fp32

    const int smem_bytes = ((BT + BK) * PADW + BT + BK) * (int)sizeof(float); // ~68KB
    cudaFuncSetAttribute(mmd_band_kernel,
                         cudaFuncAttributeMaxDynamicSharedMemorySize, smem_bytes);

    dim3 grid(NKT, T_LEN / BT);   // (9, 32) = 288 blocks -> 2 CTAs/SM, one wave
    mmd_band_kernel<<<grid, NTHR, smem_bytes>>>(x, init, out);
}